// round 13
// baseline (speedup 1.0000x reference)
#include <cuda_runtime.h>
#include <cstdint>

// Dims: N=32, K=32, T=128, H=768
#define NN 32
#define KK 32
#define TT 128
#define HH 768
#define H2 1536

// Output layout (float32 concat)
#define OFF_SCORE 0
#define OFF_ENC   1024
#define OFF_MASK  (1024 + 3145728)
#define OFF_USE   (OFF_MASK + 4096)
#define OFF_IDX   (OFF_USE + 24576)

// Scratch
__device__ float g_cqk[NN * HH];        // cqk_pro [n][g] (bias folded)
__device__ float g_c[NN];               // b_k . cqk_pro[n]
__device__ float g_spart[24 * 1024];    // partial scores [ht][n*32+k]

// Monotonic sync state (never reset; graph replays serialize, so generations
// are derived from entry tickets).
__device__ unsigned g_kaDone;           // +384 per replay
__device__ unsigned g_k2Gen;            // +97  per replay (entry tickets)
__device__ unsigned g_tick;             // +97  per replay (finalize ticket)

// Grid layout: [kA 384 | prefetch 16 | gather 3128 | k2 97]
#define KA_BLOCKS 384
#define PF_BLOCKS 16
#define KD_ITEMS  (786432 + 6144 + 4096 + 4096)   // 800768
#define KD_BLOCKS ((KD_ITEMS + 255) / 256)        // 3128
#define K2_BASE   (KA_BLOCKS + PF_BLOCKS + KD_BLOCKS)   // 3528
#define GRID_ALL  (K2_BASE + 97)                        // 3625

__global__ void __launch_bounds__(256) k_fused(
    const float* __restrict__ ctx,      // (N,3,H)
    const float* __restrict__ tracked,  // (N,H)
    const float* __restrict__ W_cqk,    // (H,2H)
    const float* __restrict__ b_cqk,    // (H,)
    const float* __restrict__ p0,       // (N,K,T,H)
    const float* __restrict__ p1,       // (N,K,H)
    const int*   __restrict__ pmask,    // (N,K,T) bool-as-int32
    const int*   __restrict__ label,    // (N,)
    const int*   __restrict__ ptok,     // (N,K,T)
    const int*   __restrict__ ck_mask,  // (N,K) bool-as-int32
    const float* __restrict__ W_k,      // (H,H)
    const float* __restrict__ b_k,      // (H,)
    float* __restrict__ out)
{
    // k2-role smem (27.6 KB), overlaid:
    //   phase A: float sc[768*9]                      (27648 B)
    //   phase B: float4 red[16*64] | vtile at +16384  (17408 B)
    __shared__ __align__(16) unsigned char sm[27648];
    __shared__ int s_final;

    int blk = blockIdx.x;
    int tid = threadIdx.x;

    if (blk < KA_BLOCKS) {
        // ---- kA (R7 verbatim): warp = (g, ngroup of 8 n) ----
        int gw   = blk * 8 + (tid >> 5);        // 0..3071
        int lane = tid & 31;
        int g    = gw >> 2;
        int n0   = (gw & 3) * 8;

        const float4* W4 = reinterpret_cast<const float4*>(W_cqk + (size_t)g * H2);

        float acc[8];
#pragma unroll
        for (int nn = 0; nn < 8; ++nn) acc[nn] = 0.f;

#pragma unroll
        for (int i = 0; i < 6; ++i) {
            int j = lane + 32 * i;              // 0..191
            float4 w  = W4[j];
            float4 w2 = W4[192 + j];
#pragma unroll
            for (int nn = 0; nn < 8; ++nn) {
                int n = n0 + nn;
                float4 x  = reinterpret_cast<const float4*>(
                    ctx + ((size_t)n * 3 + 2) * HH)[j];
                float4 x2 = reinterpret_cast<const float4*>(
                    tracked + (size_t)n * HH)[j];
                float s = acc[nn];
                s = fmaf(w.x,  x.x,  s); s = fmaf(w.y,  x.y,  s);
                s = fmaf(w.z,  x.z,  s); s = fmaf(w.w,  x.w,  s);
                s = fmaf(w2.x, x2.x, s); s = fmaf(w2.y, x2.y, s);
                s = fmaf(w2.z, x2.z, s); s = fmaf(w2.w, x2.w, s);
                acc[nn] = s;
            }
        }
        float bg = __ldg(b_cqk + g);
#pragma unroll
        for (int nn = 0; nn < 8; ++nn) {
            float s = acc[nn];
#pragma unroll
            for (int o = 16; o > 0; o >>= 1) s += __shfl_down_sync(0xffffffffu, s, o);
            if (lane == 0) g_cqk[(size_t)(n0 + nn) * HH + g] = s + bg;
        }
        __syncthreads();
        if (tid == 0) {
            __threadfence();
            atomicAdd(&g_kaDone, 1u);
        }
        return;
    }

    if (blk < KA_BLOCKS + PF_BLOCKS) {
        // ---- L2 prefetch: p1 (3MB) + W_k (2.25MB) ----
        int pidx = (blk - KA_BLOCKS) * 256 + tid;
        const char* b1 = (const char*)p1;
        const char* b2 = (const char*)W_k;
        for (int i = pidx; i < 24576; i += PF_BLOCKS * 256)
            asm volatile("prefetch.global.L2 [%0];" :: "l"(b1 + (size_t)i * 128));
        for (int i = pidx; i < 18432; i += PF_BLOCKS * 256)
            asm volatile("prefetch.global.L2 [%0];" :: "l"(b2 + (size_t)i * 128));
        return;
    }

    if (blk < K2_BASE) {
        // ---- gather (R7 verbatim) ----
        int idx = (blk - KA_BLOCKS - PF_BLOCKS) * 256 + tid;
        const int ENC_F4 = NN * TT * HH / 4;    // 786432
        const int USE_F4 = NN * HH / 4;         // 6144
        const int MT     = NN * TT;             // 4096

        if (idx < ENC_F4) {
            int per_n = TT * HH / 4;            // 24576
            int n = idx / per_n;
            int r = idx - n * per_n;
            int lab = __ldg(label + n);
            const float4* src = reinterpret_cast<const float4*>(
                p0 + ((size_t)(n * KK + lab)) * TT * HH);
            float4* dst = reinterpret_cast<float4*>(out + OFF_ENC + (size_t)n * TT * HH);
            dst[r] = src[r];
            return;
        }
        idx -= ENC_F4;
        if (idx < USE_F4) {
            int per_n = HH / 4;                 // 192
            int n = idx / per_n;
            int r = idx - n * per_n;
            int lab = __ldg(label + n);
            const float4* src = reinterpret_cast<const float4*>(
                p1 + ((size_t)(n * KK + lab)) * HH);
            float4* dst = reinterpret_cast<float4*>(out + OFF_USE + (size_t)n * HH);
            dst[r] = src[r];
            return;
        }
        idx -= USE_F4;
        if (idx < MT) {
            int n = idx / TT;
            int t = idx - n * TT;
            int lab = __ldg(label + n);
            out[OFF_MASK + idx] = (pmask[((size_t)(n * KK + lab)) * TT + t] != 0) ? 1.0f : 0.0f;
            return;
        }
        idx -= MT;
        if (idx < MT) {
            int n = idx / TT;
            int t = idx - n * TT;
            int lab = __ldg(label + n);
            out[OFF_IDX + idx] = (float)ptok[((size_t)(n * KK + lab)) * TT + t];
            return;
        }
        return;
    }

    // ======================= k2 role (97 blocks, dispatched last) ==========
    // Entry wait: all 384 kA blocks of THIS replay generation done.
    if (tid == 0) {
        unsigned gen = atomicAdd(&g_k2Gen, 1u) / 97u;
        unsigned target = (gen + 1u) * (unsigned)KA_BLOCKS;
        volatile unsigned* p = &g_kaDone;
        while (*p < target) __nanosleep(64);
        __threadfence();
    }
    __syncthreads();

    int k2b = blk - K2_BASE;                    // 0..96

    if (k2b < 96) {
        float* sc = reinterpret_cast<float*>(sm);        // [g][nn] stride 9

        int ngrp = k2b / 24;
        int ht   = k2b - ngrp * 24;
        int n0   = ngrp * 8;
        int h0   = ht * 32;
        int gsub = tid >> 3;                    // 0..31
        int hf4  = tid & 7;                     // 0..7
        int h    = h0 + hf4 * 4;

        for (int s = tid; s < 8 * HH; s += 256) {
            int nn = s / HH;
            int g  = s - nn * HH;
            sc[g * 9 + nn] = g_cqk[(size_t)(n0 + nn) * HH + g];
        }
        __syncthreads();

        float4 acc[8];
#pragma unroll
        for (int nn = 0; nn < 8; ++nn) acc[nn] = make_float4(0.f, 0.f, 0.f, 0.f);

        int g0 = gsub * 24;
#pragma unroll 6
        for (int i = 0; i < 24; ++i) {
            int g = g0 + i;
            float4 wv = __ldg(reinterpret_cast<const float4*>(W_k + (size_t)g * HH + h));
#pragma unroll
            for (int nn = 0; nn < 8; ++nn) {
                float x = sc[g * 9 + nn];
                acc[nn].x = fmaf(wv.x, x, acc[nn].x);
                acc[nn].y = fmaf(wv.y, x, acc[nn].y);
                acc[nn].z = fmaf(wv.z, x, acc[nn].z);
                acc[nn].w = fmaf(wv.w, x, acc[nn].w);
            }
        }
        __syncthreads();                        // sc dead; reuse smem

        float4* red   = reinterpret_cast<float4*>(sm);          // 16*64 f4
        float*  vtile = reinterpret_cast<float*>(sm + 16384);   // [nn][32]

        // cascaded halving over gsub (32 -> 1)
#pragma unroll
        for (int step = 16; step >= 1; step >>= 1) {
            if (gsub >= step && gsub < 2 * step) {
#pragma unroll
                for (int nn = 0; nn < 8; ++nn)
                    red[(gsub - step) * 64 + hf4 * 8 + nn] = acc[nn];
            }
            __syncthreads();
            if (gsub < step) {
#pragma unroll
                for (int nn = 0; nn < 8; ++nn) {
                    float4 p = red[gsub * 64 + hf4 * 8 + nn];
                    acc[nn].x += p.x; acc[nn].y += p.y;
                    acc[nn].z += p.z; acc[nn].w += p.w;
                }
            }
            __syncthreads();
        }

        if (gsub == 0) {
#pragma unroll
            for (int nn = 0; nn < 8; ++nn)
                *reinterpret_cast<float4*>(&vtile[nn * 32 + hf4 * 4]) = acc[nn];
        }
        __syncthreads();

        // partial scores: thread = (nn = tid>>5, k = tid&31)
        {
            int nn = tid >> 5;
            int k  = tid & 31;
            int n  = n0 + nn;
            const float4* prow = reinterpret_cast<const float4*>(
                p1 + ((size_t)n * KK + k) * HH + h0);
            float4 a[8];
#pragma unroll
            for (int i = 0; i < 8; ++i) a[i] = prow[i];
            float s = 0.f;
#pragma unroll
            for (int i = 0; i < 8; ++i) {
                s = fmaf(a[i].x, vtile[nn * 32 + i * 4 + 0], s);
                s = fmaf(a[i].y, vtile[nn * 32 + i * 4 + 1], s);
                s = fmaf(a[i].z, vtile[nn * 32 + i * 4 + 2], s);
                s = fmaf(a[i].w, vtile[nn * 32 + i * 4 + 3], s);
            }
            g_spart[ht * 1024 + n * 32 + k] = s;
        }
    } else {
        // c[n] = b_k . cqk[n,:]
        float* cred = reinterpret_cast<float*>(sm);     // 32*9
        int n = tid >> 3;
        int q = tid & 7;
        float s = 0.f;
        for (int i = 0; i < 96; ++i) {
            int g = q * 96 + i;
            s = fmaf(__ldg(b_k + g), g_cqk[(size_t)n * HH + g], s);
        }
        cred[n * 9 + q] = s;
        __syncthreads();
        if (tid < 32) {
            float t = 0.f;
#pragma unroll
            for (int j = 0; j < 8; ++j) t += cred[tid * 9 + j];
            g_c[tid] = t;
        }
    }

    // last-ticket finalize (monotonic mod-97)
    __threadfence();
    __syncthreads();
    if (tid == 0) {
        unsigned t = atomicAdd(&g_tick, 1u);
        s_final = ((t % 97u) == 96u) ? 1 : 0;
    }
    __syncthreads();
    if (s_final) {
        __threadfence();
#pragma unroll
        for (int u = 0; u < 4; ++u) {
            int idx = tid + u * 256;            // 0..1023
            int n = idx >> 5;
            float s = 0.f;
#pragma unroll 8
            for (int ht = 0; ht < 24; ++ht)
                s += g_spart[ht * 1024 + idx];
            s += g_c[n];
            if (ck_mask[idx] == 0) s = -1e20f;
            out[OFF_SCORE + idx] = s;
        }
    }
}

extern "C" void kernel_launch(void* const* d_in, const int* in_sizes, int n_in,
                              void* d_out, int out_size) {
    const float* ctx     = (const float*)d_in[0];
    const float* tracked = (const float*)d_in[1];
    const float* p0      = (const float*)d_in[2];
    const float* p1      = (const float*)d_in[3];
    const int*   pmask   = (const int*)d_in[4];
    const int*   ckmask  = (const int*)d_in[5];
    const int*   label   = (const int*)d_in[6];
    const int*   ptok    = (const int*)d_in[7];
    const float* W_cqk   = (const float*)d_in[8];
    const float* b_cqk   = (const float*)d_in[9];
    const float* W_k     = (const float*)d_in[10];
    const float* b_k     = (const float*)d_in[11];
    float* out = (float*)d_out;

    k_fused<<<GRID_ALL, 256>>>(ctx, tracked, W_cqk, b_cqk,
                               p0, p1, pmask, label, ptok, ckmask,
                               W_k, b_k, out);
}

// round 15
// speedup vs baseline: 1.2704x; 1.2704x over previous
#include <cuda_runtime.h>
#include <cstdint>

// Dims: N=32, K=32, T=128, H=768
#define NN 32
#define KK 32
#define TT 128
#define HH 768
#define H2 1536

// Output layout (float32 concat)
#define OFF_SCORE 0
#define OFF_ENC   1024
#define OFF_MASK  (1024 + 3145728)
#define OFF_USE   (OFF_MASK + 4096)
#define OFF_IDX   (OFF_USE + 24576)

// Scratch
__device__ float g_cqk[NN * HH];   // cqk_pro [n][g] (bias folded)
__device__ float g_v[NN * HH];     // v [n][h]
__device__ float g_c[NN];          // b_k . cqk_pro[n]

// ---------------------------------------------------------------------------
// kA kernel (+ L2 prefetch blocks): R7 verbatim math.
//   blocks [0,384): warp = (g, ngroup of 8 n), lanes split W row.
//   blocks [384,400): prefetch p1 + W_k into L2 for k2/k3.
// ---------------------------------------------------------------------------
#define KA_BLOCKS 384
#define PF_BLOCKS 16

__global__ void __launch_bounds__(256) kA(
    const float* __restrict__ ctx,      // (N,3,H)
    const float* __restrict__ tracked,  // (N,H)
    const float* __restrict__ W_cqk,    // (H,2H)
    const float* __restrict__ b_cqk,    // (H,)
    const float* __restrict__ p1,       // (N,K,H)  (prefetch only)
    const float* __restrict__ W_k)      // (H,H)    (prefetch only)
{
    int blk = blockIdx.x;
    int tid = threadIdx.x;

    if (blk >= KA_BLOCKS) {
        int pidx = (blk - KA_BLOCKS) * 256 + tid;
        const char* b1 = (const char*)p1;
        const char* b2 = (const char*)W_k;
        for (int i = pidx; i < 24576; i += PF_BLOCKS * 256)
            asm volatile("prefetch.global.L2 [%0];" :: "l"(b1 + (size_t)i * 128));
        for (int i = pidx; i < 18432; i += PF_BLOCKS * 256)
            asm volatile("prefetch.global.L2 [%0];" :: "l"(b2 + (size_t)i * 128));
        return;
    }

    int gw   = blk * 8 + (tid >> 5);            // 0..3071
    int lane = tid & 31;
    int g    = gw >> 2;
    int n0   = (gw & 3) * 8;

    const float4* W4 = reinterpret_cast<const float4*>(W_cqk + (size_t)g * H2);

    float acc[8];
#pragma unroll
    for (int nn = 0; nn < 8; ++nn) acc[nn] = 0.f;

#pragma unroll
    for (int i = 0; i < 6; ++i) {
        int j = lane + 32 * i;                  // 0..191
        float4 w  = W4[j];
        float4 w2 = W4[192 + j];
#pragma unroll
        for (int nn = 0; nn < 8; ++nn) {
            int n = n0 + nn;
            float4 x  = reinterpret_cast<const float4*>(
                ctx + ((size_t)n * 3 + 2) * HH)[j];
            float4 x2 = reinterpret_cast<const float4*>(
                tracked + (size_t)n * HH)[j];
            float s = acc[nn];
            s = fmaf(w.x,  x.x,  s); s = fmaf(w.y,  x.y,  s);
            s = fmaf(w.z,  x.z,  s); s = fmaf(w.w,  x.w,  s);
            s = fmaf(w2.x, x2.x, s); s = fmaf(w2.y, x2.y, s);
            s = fmaf(w2.z, x2.z, s); s = fmaf(w2.w, x2.w, s);
            acc[nn] = s;
        }
    }
    float bg = __ldg(b_cqk + g);
#pragma unroll
    for (int nn = 0; nn < 8; ++nn) {
        float s = acc[nn];
#pragma unroll
        for (int o = 16; o > 0; o >>= 1) s += __shfl_down_sync(0xffffffffu, s, o);
        if (lane == 0) g_cqk[(size_t)(n0 + nn) * HH + g] = s + bg;
    }
}

// ---------------------------------------------------------------------------
// Gather kernel: R7 verbatim indexing. Runs on forked stream (independent).
// ---------------------------------------------------------------------------
#define KD_ITEMS  (786432 + 6144 + 4096 + 4096)   // 800768
#define KD_BLOCKS ((KD_ITEMS + 255) / 256)        // 3128

__global__ void __launch_bounds__(256) k_gather(
    const float* __restrict__ p0,        // (N,K,T,H)
    const float* __restrict__ p1,        // (N,K,H)
    const int*   __restrict__ pmask,     // (N,K,T) bool-as-int32
    const int*   __restrict__ label,     // (N,)
    const int*   __restrict__ ptok,      // (N,K,T)
    float* __restrict__ out)
{
    int idx = blockIdx.x * 256 + threadIdx.x;
    const int ENC_F4 = NN * TT * HH / 4;        // 786432
    const int USE_F4 = NN * HH / 4;             // 6144
    const int MT     = NN * TT;                 // 4096

    if (idx < ENC_F4) {
        int per_n = TT * HH / 4;                // 24576
        int n = idx / per_n;
        int r = idx - n * per_n;
        int lab = __ldg(label + n);
        const float4* src = reinterpret_cast<const float4*>(
            p0 + ((size_t)(n * KK + lab)) * TT * HH);
        float4* dst = reinterpret_cast<float4*>(out + OFF_ENC + (size_t)n * TT * HH);
        dst[r] = src[r];
        return;
    }
    idx -= ENC_F4;
    if (idx < USE_F4) {
        int per_n = HH / 4;                     // 192
        int n = idx / per_n;
        int r = idx - n * per_n;
        int lab = __ldg(label + n);
        const float4* src = reinterpret_cast<const float4*>(
            p1 + ((size_t)(n * KK + lab)) * HH);
        float4* dst = reinterpret_cast<float4*>(out + OFF_USE + (size_t)n * HH);
        dst[r] = src[r];
        return;
    }
    idx -= USE_F4;
    if (idx < MT) {
        int n = idx / TT;
        int t = idx - n * TT;
        int lab = __ldg(label + n);
        out[OFF_MASK + idx] = (pmask[((size_t)(n * KK + lab)) * TT + t] != 0) ? 1.0f : 0.0f;
        return;
    }
    idx -= MT;
    if (idx < MT) {
        int n = idx / TT;
        int t = idx - n * TT;
        int lab = __ldg(label + n);
        out[OFF_IDX + idx] = (float)ptok[((size_t)(n * KK + lab)) * TT + t];
        return;
    }
}

// ---------------------------------------------------------------------------
// K2 (R7 verbatim): v[n,h] = sum_g cqk[n,g] * W_k[g,h];  block 96: c[n].
// ---------------------------------------------------------------------------
__global__ void __launch_bounds__(128) k2_v(
    const float* __restrict__ W_k,   // (H,H)
    const float* __restrict__ b_k)   // (H,)
{
    __shared__ float sc[HH * 9];                // [g][nn] stride 9 (27.6KB)
    __shared__ float red[4 * 32 * 9];           // [gsub][hl][nn] stride 9

    int blk = blockIdx.x;
    int tid = threadIdx.x;

    if (blk < 96) {
        int ht   = blk % 24;
        int ngrp = blk / 24;
        int n0   = ngrp * 8;
        int h0   = ht * 32;
        int hl   = tid & 31;
        int gsub = tid >> 5;                    // 0..3

        for (int s = tid; s < 8 * HH; s += 128) {
            int nn = s / HH;
            int g  = s - nn * HH;
            sc[g * 9 + nn] = g_cqk[(size_t)(n0 + nn) * HH + g];
        }
        __syncthreads();

        float acc[8];
#pragma unroll
        for (int nn = 0; nn < 8; ++nn) acc[nn] = 0.f;

        int gbase = gsub * 192;
#pragma unroll 8
        for (int i = 0; i < 192; ++i) {
            int g = gbase + i;
            float wv = __ldg(W_k + (size_t)g * HH + h0 + hl);
#pragma unroll
            for (int nn = 0; nn < 8; ++nn)
                acc[nn] = fmaf(wv, sc[g * 9 + nn], acc[nn]);
        }

#pragma unroll
        for (int nn = 0; nn < 8; ++nn) red[(gsub * 32 + hl) * 9 + nn] = acc[nn];
        __syncthreads();

        for (int o = tid; o < 256; o += 128) {
            int ohl = o >> 3;
            int onn = o & 7;
            float s = red[(0 * 32 + ohl) * 9 + onn] + red[(1 * 32 + ohl) * 9 + onn]
                    + red[(2 * 32 + ohl) * 9 + onn] + red[(3 * 32 + ohl) * 9 + onn];
            g_v[(size_t)(n0 + onn) * HH + h0 + ohl] = s;
        }
        return;
    }

    // c[n] = b_k . cqk[n,:]  (block 96)
    __shared__ float cred[32 * 5];
    int n = tid >> 2;
    int q = tid & 3;
    float s = 0.f;
    for (int i = 0; i < 192; ++i) {
        int g = q * 192 + i;
        s = fmaf(__ldg(b_k + g), g_cqk[(size_t)n * HH + g], s);
    }
    cred[n * 5 + q] = s;
    __syncthreads();
    if (tid < 32)
        g_c[tid] = cred[tid * 5 + 0] + cred[tid * 5 + 1]
                 + cred[tid * 5 + 2] + cred[tid * 5 + 3];
}

// ---------------------------------------------------------------------------
// K3 (R7 verbatim): score[n,k] = p1[n,k,:].v[n,:] + c[n], masked.
// ---------------------------------------------------------------------------
__global__ void __launch_bounds__(256) k3_score(
    const float* __restrict__ p1,        // (N,K,H)
    const int* __restrict__ ck_mask,     // (N,K) bool-as-int32
    float* __restrict__ out)
{
    int wid  = blockIdx.x * 8 + (threadIdx.x >> 5);
    int lane = threadIdx.x & 31;
    int n = wid / KK;
    int k = wid - n * KK;

    const float4* p4 = reinterpret_cast<const float4*>(p1 + ((size_t)n * KK + k) * HH);
    const float4* v4 = reinterpret_cast<const float4*>(g_v + (size_t)n * HH);

    float s = 0.f;
#pragma unroll
    for (int j = lane; j < 192; j += 32) {
        float4 a = p4[j];
        float4 b = v4[j];
        s = fmaf(a.x, b.x, s); s = fmaf(a.y, b.y, s);
        s = fmaf(a.z, b.z, s); s = fmaf(a.w, b.w, s);
    }
#pragma unroll
    for (int o = 16; o > 0; o >>= 1) s += __shfl_down_sync(0xffffffffu, s, o);
    if (lane == 0) {
        s += g_c[n];
        if (ck_mask[n * KK + k] == 0) s = -1e20f;
        out[OFF_SCORE + n * KK + k] = s;
    }
}

// ---------------------------------------------------------------------------
// Launch: graph with two parallel branches.
//   branch A (forked stream): gather          (independent of everything)
//   branch B (main stream):   kA -> k2 -> k3  (dependent chain)
// Streams/events created lazily once (resources, not device memory; the work
// per call is identical and deterministic).
// ---------------------------------------------------------------------------
extern "C" void kernel_launch(void* const* d_in, const int* in_sizes, int n_in,
                              void* d_out, int out_size) {
    const float* ctx     = (const float*)d_in[0];
    const float* tracked = (const float*)d_in[1];
    const float* p0      = (const float*)d_in[2];
    const float* p1      = (const float*)d_in[3];
    const int*   pmask   = (const int*)d_in[4];
    const int*   ckmask  = (const int*)d_in[5];
    const int*   label   = (const int*)d_in[6];
    const int*   ptok    = (const int*)d_in[7];
    const float* W_cqk   = (const float*)d_in[8];
    const float* b_cqk   = (const float*)d_in[9];
    const float* W_k     = (const float*)d_in[10];
    const float* b_k     = (const float*)d_in[11];
    float* out = (float*)d_out;

    static cudaStream_t s2 = nullptr;
    static cudaEvent_t  evFork = nullptr, evJoin = nullptr;
    if (s2 == nullptr) {
        cudaStreamCreateWithFlags(&s2, cudaStreamNonBlocking);
        cudaEventCreateWithFlags(&evFork, cudaEventDisableTiming);
        cudaEventCreateWithFlags(&evJoin, cudaEventDisableTiming);
    }

    // Fork: branch A = gather on s2
    cudaEventRecord(evFork, 0);
    cudaStreamWaitEvent(s2, evFork, 0);
    k_gather<<<KD_BLOCKS, 256, 0, s2>>>(p0, p1, pmask, label, ptok, out);

    // Branch B on main stream: kA -> k2 -> k3
    kA<<<KA_BLOCKS + PF_BLOCKS, 256>>>(ctx, tracked, W_cqk, b_cqk, p1, W_k);
    k2_v<<<97, 128>>>(W_k, b_k);
    k3_score<<<(NN * KK) / 8, 256>>>(p1, ckmask, out);

    // Join branch A back into main stream
    cudaEventRecord(evJoin, s2);
    cudaStreamWaitEvent(0, evJoin, 0);
}